// round 4
// baseline (speedup 1.0000x reference)
#include <cuda_runtime.h>
#include <cuda_bf16.h>

// ---------------------------------------------------------------------------
// GCN: 3x GCNConv (64->64->64->32) + global mean pool over 64 graphs.
// N=100000 nodes, E=1600000 edges. CSR-by-dst gather formulation:
//   g[i]   = dinv[i] * (act(prev[i]) @ W)
//   out[r] = dinv[r] * (g[r] + sum_{e: dst=r} g[src(e)])
// bias of layer L is fused into the staging load of layer L+1 (or the pool).
// ---------------------------------------------------------------------------

#define N_MAX 100000
#define E_MAX 1600000
#define G_MAX 64

__device__ int   g_is64;                  // 1 if edge_index/batch are int64
__device__ int   g_deg[N_MAX];
__device__ float g_dinv[N_MAX];
__device__ int   g_rowptr[N_MAX + 1];
__device__ int   g_cursor[N_MAX];
__device__ int   g_blocksums[256];
__device__ int   g_col[E_MAX];
__device__ float g_bufA[(size_t)N_MAX * 64];
__device__ float g_bufB[(size_t)N_MAX * 64];
__device__ float g_sums[G_MAX * 32];
__device__ int   g_cnt[G_MAX];

// ---- index load helper: int32 or int64 decided at runtime ------------------
__device__ __forceinline__ int load_idx(const void* p, long long i, int is64) {
    if (is64) return (int)(((const long long*)p)[i]);
    return ((const int*)p)[i];
}

// ---- dtype detection: int64 values < 2^31 => every high word is zero -------
__global__ void k_detect(const unsigned int* w, int npairs) {
    __shared__ int any;
    if (threadIdx.x == 0) any = 0;
    __syncthreads();
    for (int i = threadIdx.x; i < npairs; i += blockDim.x) {
        if (w[2 * i + 1] != 0u) any = 1;
    }
    __syncthreads();
    if (threadIdx.x == 0) g_is64 = (any == 0) ? 1 : 0;
}

// ---- zero scratch ----------------------------------------------------------
__global__ void k_zero(int N) {
    int i = blockIdx.x * blockDim.x + threadIdx.x;
    if (i < N) g_deg[i] = 0;
    if (i < G_MAX * 32) g_sums[i] = 0.0f;
    if (i < G_MAX) g_cnt[i] = 0;
}

// ---- in-degree over dst ----------------------------------------------------
__global__ void k_degree(const void* ei, int E) {
    int e = blockIdx.x * blockDim.x + threadIdx.x;
    if (e >= E) return;
    int d = load_idx(ei, (long long)E + e, g_is64);
    atomicAdd(&g_deg[d], 1);
}

__global__ void k_dinv(int N) {
    int i = blockIdx.x * blockDim.x + threadIdx.x;
    if (i >= N) return;
    g_dinv[i] = rsqrtf((float)(g_deg[i] + 1));   // +1 self loop
}

// ---- block-level inclusive scan of degrees (exclusive rowptr within block)
__global__ void k_scan1(int N) {
    __shared__ int sh[1024];
    int tid = threadIdx.x;
    int i = blockIdx.x * 1024 + tid;
    int v = (i < N) ? g_deg[i] : 0;
    sh[tid] = v;
    __syncthreads();
    for (int off = 1; off < 1024; off <<= 1) {
        int t = (tid >= off) ? sh[tid - off] : 0;
        __syncthreads();
        sh[tid] += t;
        __syncthreads();
    }
    int incl = sh[tid];
    if (i < N) g_rowptr[i] = incl - v;
    if (tid == 1023) g_blocksums[blockIdx.x] = incl;
}

__global__ void k_scan2(int nb, int N) {
    if (threadIdx.x == 0 && blockIdx.x == 0) {
        int acc = 0;
        for (int b = 0; b < nb; b++) {
            int s = g_blocksums[b];
            g_blocksums[b] = acc;
            acc += s;
        }
        g_rowptr[N] = acc;
    }
}

__global__ void k_scan3(int N) {
    int i = blockIdx.x * blockDim.x + threadIdx.x;
    if (i >= N) return;
    int r = g_rowptr[i] + g_blocksums[i >> 10];
    g_rowptr[i] = r;
    g_cursor[i] = r;
}

// ---- fill CSR column indices ----------------------------------------------
__global__ void k_fill(const void* ei, int E) {
    int e = blockIdx.x * blockDim.x + threadIdx.x;
    if (e >= E) return;
    int is64 = g_is64;
    int s = load_idx(ei, e, is64);
    int d = load_idx(ei, (long long)E + e, is64);
    int pos = atomicAdd(&g_cursor[d], 1);
    g_col[pos] = s;
}

// ---- fused GEMM: out[n] = dinv[n] * (act(in[n] + bprev) @ W) ---------------
// MODE 0: identity (layer 1, in = x).  MODE 1: relu(in + b).  MODE 2: in + b.
template <int FOUT, int MODE>
__global__ void k_gemm(const float* __restrict__ in, const float* __restrict__ W,
                       const float* __restrict__ bprev, float* __restrict__ out,
                       int N) {
    const int FIN = 64;
    const int NT  = (FOUT == 64) ? 64 : 128;     // nodes per block
    const int LDX = NT + 4;                      // keep float4 alignment
    __shared__ float Ws[FIN * FOUT];
    __shared__ float Xst[FIN * LDX];             // transposed: [k][node]

    for (int i = threadIdx.x; i < FIN * FOUT; i += 256) Ws[i] = __ldg(&W[i]);

    int n0 = blockIdx.x * NT;

    // stage NT node rows (with prologue transform), transposed into shared
    for (int q = threadIdx.x; q < NT * 16; q += 256) {
        int node = q >> 4;
        int kq   = q & 15;                        // float4 index along k
        float4 v = make_float4(0.f, 0.f, 0.f, 0.f);
        int n = n0 + node;
        if (n < N) {
            v = *reinterpret_cast<const float4*>(in + (size_t)n * 64 + 4 * kq);
            if (MODE == 1) {
                float4 b4 = *reinterpret_cast<const float4*>(bprev + 4 * kq);
                v.x = fmaxf(v.x + b4.x, 0.f);
                v.y = fmaxf(v.y + b4.y, 0.f);
                v.z = fmaxf(v.z + b4.z, 0.f);
                v.w = fmaxf(v.w + b4.w, 0.f);
            } else if (MODE == 2) {
                float4 b4 = *reinterpret_cast<const float4*>(bprev + 4 * kq);
                v.x += b4.x; v.y += b4.y; v.z += b4.z; v.w += b4.w;
            }
        }
        Xst[(4 * kq + 0) * LDX + node] = v.x;
        Xst[(4 * kq + 1) * LDX + node] = v.y;
        Xst[(4 * kq + 2) * LDX + node] = v.z;
        Xst[(4 * kq + 3) * LDX + node] = v.w;
    }
    __syncthreads();

    const int FQ = FOUT / 4;
    int fq = threadIdx.x % FQ;
    int nq = threadIdx.x / FQ;                    // 0 .. NT/4-1

    float acc[4][4];
#pragma unroll
    for (int i = 0; i < 4; i++)
#pragma unroll
        for (int j = 0; j < 4; j++) acc[i][j] = 0.f;

#pragma unroll
    for (int k = 0; k < 64; k++) {
        float4 xv = *reinterpret_cast<const float4*>(&Xst[k * LDX + 4 * nq]);
        float4 wv = *reinterpret_cast<const float4*>(&Ws[k * FOUT + 4 * fq]);
        acc[0][0] += xv.x * wv.x; acc[0][1] += xv.x * wv.y;
        acc[0][2] += xv.x * wv.z; acc[0][3] += xv.x * wv.w;
        acc[1][0] += xv.y * wv.x; acc[1][1] += xv.y * wv.y;
        acc[1][2] += xv.y * wv.z; acc[1][3] += xv.y * wv.w;
        acc[2][0] += xv.z * wv.x; acc[2][1] += xv.z * wv.y;
        acc[2][2] += xv.z * wv.z; acc[2][3] += xv.z * wv.w;
        acc[3][0] += xv.w * wv.x; acc[3][1] += xv.w * wv.y;
        acc[3][2] += xv.w * wv.z; acc[3][3] += xv.w * wv.w;
    }

#pragma unroll
    for (int i = 0; i < 4; i++) {
        int n = n0 + 4 * nq + i;
        if (n < N) {
            float dv = g_dinv[n];
            float4 o = make_float4(dv * acc[i][0], dv * acc[i][1],
                                   dv * acc[i][2], dv * acc[i][3]);
            *reinterpret_cast<float4*>(out + (size_t)n * FOUT + 4 * fq) = o;
        }
    }
}

// ---- CSR SpMM: out[r] = dinv[r] * (g[r] + sum g[col[e]]), warp per row -----
template <int F>
__global__ void k_spmm(const float* __restrict__ gbuf, float* __restrict__ out,
                       int N) {
    int warp = (blockIdx.x * blockDim.x + threadIdx.x) >> 5;
    int lane = threadIdx.x & 31;
    if (warp >= N) return;
    const int R = F / 32;
    int beg = g_rowptr[warp];
    int end = g_rowptr[warp + 1];
    float acc[R];
#pragma unroll
    for (int r = 0; r < R; r++)
        acc[r] = gbuf[(size_t)warp * F + lane + 32 * r];   // self loop
    for (int e = beg; e < end; e++) {
        int c = __ldg(&g_col[e]);
#pragma unroll
        for (int r = 0; r < R; r++)
            acc[r] += __ldg(&gbuf[(size_t)c * F + lane + 32 * r]);
    }
    float dv = g_dinv[warp];
#pragma unroll
    for (int r = 0; r < R; r++)
        out[(size_t)warp * F + lane + 32 * r] = dv * acc[r];
}

// ---- pooling ---------------------------------------------------------------
__global__ void k_pool_acc(const float* __restrict__ agg, const void* batch,
                           int N) {
    int idx = blockIdx.x * blockDim.x + threadIdx.x;
    if (idx >= N * 32) return;
    int n = idx >> 5;
    int f = idx & 31;
    int b = load_idx(batch, n, g_is64);
    atomicAdd(&g_sums[b * 32 + f], agg[(size_t)n * 32 + f]);
    if (f == 0) atomicAdd(&g_cnt[b], 1);
}

__global__ void k_pool_out(float* __restrict__ out,
                           const float* __restrict__ b3) {
    int i = blockIdx.x * blockDim.x + threadIdx.x;
    if (i >= G_MAX * 32) return;
    int gph = i >> 5;
    int f   = i & 31;
    float c = fmaxf((float)g_cnt[gph], 1.0f);
    out[i] = g_sums[i] / c + __ldg(&b3[f]);
}

// ---------------------------------------------------------------------------
extern "C" void kernel_launch(void* const* d_in, const int* in_sizes, int n_in,
                              void* d_out, int out_size) {
    int N = in_sizes[0] / 64;
    int E = in_sizes[1] / 2;
    if (N > N_MAX) N = N_MAX;
    if (E > E_MAX) E = E_MAX;

    // inputs: x, edge_index, batch, [num_graphs], W1,b1,W2,b2,W3,b3
    int base = 3;
    if (n_in >= 10 && in_sizes[3] == 1) base = 4;

    const float* x     = (const float*)d_in[0];
    const void*  ei    = d_in[1];
    const void*  batch = d_in[2];
    const float* W1 = (const float*)d_in[base + 0];
    const float* b1 = (const float*)d_in[base + 1];
    const float* W2 = (const float*)d_in[base + 2];
    const float* b2 = (const float*)d_in[base + 3];
    const float* W3 = (const float*)d_in[base + 4];
    const float* b3 = (const float*)d_in[base + 5];
    float* out = (float*)d_out;

    int npairs = (E < 2048) ? E : 2048;
    k_detect<<<1, 256>>>((const unsigned int*)ei, npairs);

    int zgrid = (N + 255) / 256;
    k_zero<<<zgrid, 256>>>(N);

    int egrid = (E + 255) / 256;
    k_degree<<<egrid, 256>>>(ei, E);

    int ngrid = (N + 255) / 256;
    k_dinv<<<ngrid, 256>>>(N);

    int nb = (N + 1023) / 1024;
    k_scan1<<<nb, 1024>>>(N);
    k_scan2<<<1, 32>>>(nb, N);
    k_scan3<<<ngrid, 256>>>(N);
    k_fill<<<egrid, 256>>>(ei, E);

    int spmm_blocks = (N + 7) / 8;   // 8 warps / block

    // layer 1: g = dinv * (x @ W1); agg1 = spmm(g)
    k_gemm<64, 0><<<(N + 63) / 64, 256>>>(x, W1, nullptr, g_bufA, N);
    k_spmm<64><<<spmm_blocks, 256>>>(g_bufA, g_bufB, N);

    // layer 2: g = dinv * (relu(agg1 + b1) @ W2); agg2 = spmm(g)
    k_gemm<64, 1><<<(N + 63) / 64, 256>>>(g_bufB, W2, b1, g_bufA, N);
    k_spmm<64><<<spmm_blocks, 256>>>(g_bufA, g_bufB, N);

    // layer 3: g = dinv * ((agg2 + b2) @ W3); agg3 = spmm(g)
    k_gemm<32, 2><<<(N + 127) / 128, 256>>>(g_bufB, W3, b2, g_bufA, N);
    k_spmm<32><<<spmm_blocks, 256>>>(g_bufA, g_bufB, N);

    // pool: mean over batch + b3
    k_pool_acc<<<(N * 32 + 255) / 256, 256>>>(g_bufB, batch, N);
    k_pool_out<<<(G_MAX * 32 + 255) / 256, 256>>>(out, b3);
}